// round 2
// baseline (speedup 1.0000x reference)
#include <cuda_runtime.h>
#include <stdint.h>

#define NMAX 65536
#define EMAX 2100000
#define H 64
#define FULL 0xffffffffu

// ---------------- scratch (device globals) ----------------------------------
__device__ float g_deg[NMAX];
__device__ float g_dis[NMAX];
__device__ int   g_cnt[NMAX];
__device__ int   g_off[NMAX + 1];
__device__ int   g_cur[NMAX];
__device__ __align__(16) int2  g_es[EMAX];        // packed {row, norm-bits}, CSR by col
__device__ __align__(16) float g_buf0[NMAX * H];
__device__ __align__(16) float g_buf1[NMAX * H];
__device__ float g_logits[NMAX];
__device__ unsigned g_maxbits;
__device__ float g_sum;

// ---------------- helpers ----------------------------------------------------
__device__ __forceinline__ float sigmoidf_(float x) {
    return 1.0f / (1.0f + __expf(-x));
}
__device__ __forceinline__ unsigned f2key(float f) {
    unsigned b = __float_as_uint(f);
    return (b & 0x80000000u) ? ~b : (b | 0x80000000u);
}
__device__ __forceinline__ float key2f(unsigned k) {
    unsigned b = (k & 0x80000000u) ? (k & 0x7fffffffu) : ~k;
    return __uint_as_float(b);
}
__device__ __forceinline__ const float* src_buf(int s) { return s ? g_buf1 : g_buf0; }
__device__ __forceinline__ float*       dst_buf(int s) { return s ? g_buf1 : g_buf0; }

// ---------------- prep kernels -----------------------------------------------
__global__ void k_init(int n) {
    int i = blockIdx.x * blockDim.x + threadIdx.x;
    if (i < n) { g_deg[i] = 1.0f; g_cnt[i] = 0; }
    if (i == 0) { g_maxbits = 0u; g_sum = 0.0f; }
}

__global__ void k_hist(const int* __restrict__ col, const float* __restrict__ w, int E) {
    int e = blockIdx.x * blockDim.x + threadIdx.x;
    if (e < E) {
        int c = col[e];
        atomicAdd(&g_deg[c], w[e]);
        atomicAdd(&g_cnt[c], 1);
    }
}

// single block: exclusive scan of g_cnt -> g_off/g_cur, plus dis = rsqrt(deg)
__global__ void k_scan(int n) {
    const int T = 1024;
    int t = threadIdx.x;
    int c = (n + T - 1) / T;
    int lo = t * c;
    int hi = min(lo + c, n);
    int s = 0;
    for (int i = lo; i < hi; i++) s += g_cnt[i];
    __shared__ int wsum[32];
    int lane = t & 31, wid = t >> 5;
    int v = s;
    #pragma unroll
    for (int o = 1; o < 32; o <<= 1) {
        int u = __shfl_up_sync(FULL, v, o);
        if (lane >= o) v += u;
    }
    if (lane == 31) wsum[wid] = v;
    __syncthreads();
    if (wid == 0) {
        int wv = wsum[lane];
        #pragma unroll
        for (int o = 1; o < 32; o <<= 1) {
            int u = __shfl_up_sync(FULL, wv, o);
            if (lane >= o) wv += u;
        }
        wsum[lane] = wv;
    }
    __syncthreads();
    int run = v - s + (wid ? wsum[wid - 1] : 0);   // exclusive prefix
    for (int i = lo; i < hi; i++) {
        g_off[i] = run; g_cur[i] = run;
        run += g_cnt[i];
        g_dis[i] = rsqrtf(g_deg[i]);   // deg >= 1 (self-loop)
    }
    if (t == T - 1) g_off[n] = run;
}

__global__ void k_scatter(const int* __restrict__ row, const int* __restrict__ col,
                          const float* __restrict__ w, int E) {
    int e = blockIdx.x * blockDim.x + threadIdx.x;
    if (e >= E) return;
    int r = row[e], c = col[e];
    float nm = g_dis[r] * w[e] * g_dis[c];
    int pos = atomicAdd(&g_cur[c], 1);
    g_es[pos] = make_int2(r, __float_as_int(nm));
}

// ---------------- layer 1 GEMM: xw = x @ W1 ----------------------------------
__global__ void k_xw1(const float* __restrict__ x, const float* __restrict__ W1,
                      int n, int F, int dst) {
    __shared__ float W1s[16 * H];   // F <= 16
    for (int idx = threadIdx.x; idx < F * H; idx += blockDim.x)
        W1s[idx] = W1[idx];
    __syncthreads();
    int i = blockIdx.x * 4 + (threadIdx.x >> 6);
    int h = threadIdx.x & 63;
    if (i >= n) return;
    const float* xr = x + (size_t)i * F;
    float acc = 0.0f;
    for (int k = 0; k < F; k++) acc = fmaf(xr[k], W1s[k * H + h], acc);
    dst_buf(dst)[i * H + h] = acc;
}

// ---------------- fused gather + sigmoid + next GEMM -------------------------
// one warp per destination node; agg = dis^2*xw[d] + sum norm*xw[r];
// h = sigmoid(agg + bprev); out = h @ W  -> other buffer.
__global__ void __launch_bounds__(256) k_gl(const float* __restrict__ W,
                                            const float* __restrict__ bprev,
                                            int n, int src) {
    __shared__ float Ws[H * H];
    __shared__ float hs[8][H];
    for (int idx = threadIdx.x; idx < H * H; idx += 256) Ws[idx] = W[idx];
    __syncthreads();
    const float* xw = src_buf(src);
    float* out = dst_buf(src ^ 1);
    int warp = threadIdx.x >> 5, lane = threadIdx.x & 31;
    int d = blockIdx.x * 8 + warp;
    if (d >= n) return;

    int start = g_off[d], end = g_off[d + 1];
    float di = g_dis[d];
    float2 self = *reinterpret_cast<const float2*>(&xw[d * H + lane * 2]);
    float ax = di * di * self.x, ay = di * di * self.y;

    int eb = start;
    for (; eb + 32 <= end; eb += 32) {
        int2 p = g_es[eb + lane];
        #pragma unroll 4
        for (int j = 0; j < 32; j++) {
            int   r  = __shfl_sync(FULL, p.x, j);
            float nm = __shfl_sync(FULL, __int_as_float(p.y), j);
            float2 v = *reinterpret_cast<const float2*>(&xw[r * H + lane * 2]);
            ax = fmaf(nm, v.x, ax);
            ay = fmaf(nm, v.y, ay);
        }
    }
    if (eb < end) {
        int rj = 0; float nmj = 0.0f;
        if (eb + lane < end) { int2 p = g_es[eb + lane]; rj = p.x; nmj = __int_as_float(p.y); }
        int cnt = end - eb;
        for (int j = 0; j < cnt; j++) {
            int   r  = __shfl_sync(FULL, rj, j);
            float nm = __shfl_sync(FULL, nmj, j);
            float2 v = *reinterpret_cast<const float2*>(&xw[r * H + lane * 2]);
            ax = fmaf(nm, v.x, ax);
            ay = fmaf(nm, v.y, ay);
        }
    }

    float h0 = sigmoidf_(ax + __ldg(&bprev[lane * 2]));
    float h1 = sigmoidf_(ay + __ldg(&bprev[lane * 2 + 1]));
    *reinterpret_cast<float2*>(&hs[warp][lane * 2]) = make_float2(h0, h1);
    __syncwarp();

    float o0 = 0.0f, o1 = 0.0f;
    #pragma unroll
    for (int k = 0; k < H; k++) {
        float hk = hs[warp][k];
        float2 wv = *reinterpret_cast<const float2*>(&Ws[k * H + lane * 2]);
        o0 = fmaf(hk, wv.x, o0);
        o1 = fmaf(hk, wv.y, o1);
    }
    *reinterpret_cast<float2*>(&out[d * H + lane * 2]) = make_float2(o0, o1);
}

// ---------------- head: gather + sigmoid + dot(Wl) + bl + max ---------------
__global__ void __launch_bounds__(256) k_ghead(const float* __restrict__ Wl,
                                               const float* __restrict__ bl,
                                               const float* __restrict__ b3,
                                               int n, int src) {
    const float* xw = src_buf(src);
    int warp = threadIdx.x >> 5, lane = threadIdx.x & 31;
    int d = blockIdx.x * 8 + warp;
    if (d >= n) return;

    int start = g_off[d], end = g_off[d + 1];
    float di = g_dis[d];
    float2 self = *reinterpret_cast<const float2*>(&xw[d * H + lane * 2]);
    float ax = di * di * self.x, ay = di * di * self.y;

    int eb = start;
    for (; eb + 32 <= end; eb += 32) {
        int2 p = g_es[eb + lane];
        #pragma unroll 4
        for (int j = 0; j < 32; j++) {
            int   r  = __shfl_sync(FULL, p.x, j);
            float nm = __shfl_sync(FULL, __int_as_float(p.y), j);
            float2 v = *reinterpret_cast<const float2*>(&xw[r * H + lane * 2]);
            ax = fmaf(nm, v.x, ax);
            ay = fmaf(nm, v.y, ay);
        }
    }
    if (eb < end) {
        int rj = 0; float nmj = 0.0f;
        if (eb + lane < end) { int2 p = g_es[eb + lane]; rj = p.x; nmj = __int_as_float(p.y); }
        int cnt = end - eb;
        for (int j = 0; j < cnt; j++) {
            int   r  = __shfl_sync(FULL, rj, j);
            float nm = __shfl_sync(FULL, nmj, j);
            float2 v = *reinterpret_cast<const float2*>(&xw[r * H + lane * 2]);
            ax = fmaf(nm, v.x, ax);
            ay = fmaf(nm, v.y, ay);
        }
    }

    float h0 = sigmoidf_(ax + __ldg(&b3[lane * 2]));
    float h1 = sigmoidf_(ay + __ldg(&b3[lane * 2 + 1]));
    float p = fmaf(h0, __ldg(&Wl[lane * 2]), h1 * __ldg(&Wl[lane * 2 + 1]));
    #pragma unroll
    for (int o = 16; o > 0; o >>= 1) p += __shfl_xor_sync(FULL, p, o);
    if (lane == 0) {
        float lg = p + __ldg(&bl[0]);
        g_logits[d] = lg;
        atomicMax(&g_maxbits, f2key(lg));
    }
}

// ---------------- softmax ----------------------------------------------------
__global__ void k_expsum(float* __restrict__ out, int n) {
    __shared__ float ssum[8];
    int i = blockIdx.x * blockDim.x + threadIdx.x;
    float mx = key2f(g_maxbits);
    float e = 0.0f;
    if (i < n) {
        e = expf(g_logits[i] - mx);
        out[i] = e;
    }
    #pragma unroll
    for (int o = 16; o > 0; o >>= 1) e += __shfl_xor_sync(FULL, e, o);
    int lane = threadIdx.x & 31, warp = threadIdx.x >> 5;
    if (lane == 0) ssum[warp] = e;
    __syncthreads();
    if (threadIdx.x == 0) {
        float s = 0.0f;
        #pragma unroll
        for (int w = 0; w < 8; w++) s += ssum[w];
        atomicAdd(&g_sum, s);
    }
}

__global__ void k_scale(float* __restrict__ out, int n) {
    int i = blockIdx.x * blockDim.x + threadIdx.x;
    if (i < n) out[i] *= (1.0f / g_sum);
}

// ---------------- launch -----------------------------------------------------
extern "C" void kernel_launch(void* const* d_in, const int* in_sizes, int n_in,
                              void* d_out, int out_size) {
    const float* x   = (const float*)d_in[0];
    const int*   edg = (const int*)d_in[1];
    const float* w   = (const float*)d_in[2];
    const float* W1  = (const float*)d_in[3];
    const float* b1  = (const float*)d_in[4];
    const float* W2  = (const float*)d_in[5];
    const float* b2  = (const float*)d_in[6];
    const float* W3  = (const float*)d_in[7];
    const float* b3  = (const float*)d_in[8];
    const float* Wl  = (const float*)d_in[9];
    const float* bl  = (const float*)d_in[10];
    float* out = (float*)d_out;

    int E = in_sizes[2];
    int F = in_sizes[3] / H;
    int n = in_sizes[0] / F;

    const int* row = edg;
    const int* col = edg + E;

    int nb_n = (n + 255) / 256;
    int nb_e = (E + 255) / 256;
    int nb_w = (n + 7) / 8;      // warp-per-node kernels

    k_init<<<nb_n, 256>>>(n);
    k_hist<<<nb_e, 256>>>(col, w, E);
    k_scan<<<1, 1024>>>(n);
    k_scatter<<<nb_e, 256>>>(row, col, w, E);

    k_xw1<<<(n + 3) / 4, 256>>>(x, W1, n, F, 0);        // -> buf0
    k_gl<<<nb_w, 256>>>(W2, b1, n, 0);                  // buf0 -> buf1
    k_gl<<<nb_w, 256>>>(W3, b2, n, 1);                  // buf1 -> buf0
    k_ghead<<<nb_w, 256>>>(Wl, bl, b3, n, 0);           // buf0 -> logits

    k_expsum<<<nb_n, 256>>>(out, n);
    k_scale<<<nb_n, 256>>>(out, n);
}

// round 3
// speedup vs baseline: 1.6187x; 1.6187x over previous
#include <cuda_runtime.h>
#include <stdint.h>

#define NMAX 65536
#define EMAX 2100000
#define H 64
#define FULL 0xffffffffu

// ---------------- scratch (device globals) ----------------------------------
__device__ float g_deg[NMAX];
__device__ float g_dis[NMAX];
__device__ int   g_cnt[NMAX];
__device__ int   g_off[NMAX + 1];
__device__ int   g_cur[NMAX];
__device__ int   g_bsum[256];
__device__ int   g_boff[256];
__device__ __align__(16) int2  g_es[EMAX];        // {row, norm-bits}, CSR by col
__device__ __align__(16) float g_buf0[NMAX * H];
__device__ __align__(16) float g_buf1[NMAX * H];
__device__ float g_logits[NMAX];
__device__ unsigned g_maxbits;
__device__ float g_sum;

// ---------------- helpers ----------------------------------------------------
__device__ __forceinline__ float sigmoidf_(float x) {
    return 1.0f / (1.0f + __expf(-x));
}
__device__ __forceinline__ unsigned f2key(float f) {
    unsigned b = __float_as_uint(f);
    return (b & 0x80000000u) ? ~b : (b | 0x80000000u);
}
__device__ __forceinline__ float key2f(unsigned k) {
    unsigned b = (k & 0x80000000u) ? (k & 0x7fffffffu) : ~k;
    return __uint_as_float(b);
}
__device__ __forceinline__ const float* src_buf(int s) { return s ? g_buf1 : g_buf0; }
__device__ __forceinline__ float*       dst_buf(int s) { return s ? g_buf1 : g_buf0; }

// ---------------- prep kernels -----------------------------------------------
__global__ void k_init(int n) {
    int i = blockIdx.x * blockDim.x + threadIdx.x;
    if (i < n) { g_deg[i] = 1.0f; g_cnt[i] = 0; }
    if (i == 0) { g_maxbits = 0u; g_sum = 0.0f; }
}

// 4 edges per thread for MLP against atomic latency
__global__ void k_hist(const int* __restrict__ col, const float* __restrict__ w, int E) {
    int base = (blockIdx.x * blockDim.x + threadIdx.x) * 4;
    if (base >= E) return;
    int m = min(4, E - base);
    int   c4[4]; float w4[4];
    #pragma unroll
    for (int j = 0; j < 4; j++) {
        int idx = (j < m) ? base + j : base;
        c4[j] = __ldg(&col[idx]);
        w4[j] = __ldg(&w[idx]);
    }
    #pragma unroll
    for (int j = 0; j < 4; j++) if (j < m) {
        atomicAdd(&g_deg[c4[j]], w4[j]);
        atomicAdd(&g_cnt[c4[j]], 1);
    }
}

// --- scan stage 1: per-256-chunk sums ---
__global__ void k_s1(int n) {
    __shared__ int ws[8];
    int t = threadIdx.x;
    int i = blockIdx.x * 256 + t;
    int v = (i < n) ? g_cnt[i] : 0;
    #pragma unroll
    for (int o = 16; o > 0; o >>= 1) v += __shfl_xor_sync(FULL, v, o);
    if ((t & 31) == 0) ws[t >> 5] = v;
    __syncthreads();
    if (t == 0) {
        int s = 0;
        #pragma unroll
        for (int wgi = 0; wgi < 8; wgi++) s += ws[wgi];
        g_bsum[blockIdx.x] = s;
    }
}

// --- scan stage 2: exclusive scan of up to 256 block sums ---
__global__ void k_s2(int B, int E, int n) {
    __shared__ int ws[8];
    int t = threadIdx.x, lane = t & 31, wd = t >> 5;
    int v = (t < B) ? g_bsum[t] : 0;
    int x = v;
    #pragma unroll
    for (int o = 1; o < 32; o <<= 1) {
        int u = __shfl_up_sync(FULL, x, o);
        if (lane >= o) x += u;
    }
    if (lane == 31) ws[wd] = x;
    __syncthreads();
    if (wd == 0) {
        int y = (lane < 8) ? ws[lane] : 0;
        #pragma unroll
        for (int o = 1; o < 8; o <<= 1) {
            int u = __shfl_up_sync(FULL, y, o);
            if (lane >= o) y += u;
        }
        if (lane < 8) ws[lane] = y;
    }
    __syncthreads();
    int incl = x + (wd ? ws[wd - 1] : 0);
    if (t < B) g_boff[t] = incl - v;      // exclusive
    if (t == 0) g_off[n] = E;
}

// --- scan stage 3: local exclusive scan + fixup; also dis = rsqrt(deg) ---
__global__ void k_s3(int n) {
    __shared__ int ws[8];
    int t = threadIdx.x, lane = t & 31, wd = t >> 5;
    int i = blockIdx.x * 256 + t;
    int v = (i < n) ? g_cnt[i] : 0;
    int x = v;
    #pragma unroll
    for (int o = 1; o < 32; o <<= 1) {
        int u = __shfl_up_sync(FULL, x, o);
        if (lane >= o) x += u;
    }
    if (lane == 31) ws[wd] = x;
    __syncthreads();
    if (wd == 0) {
        int y = (lane < 8) ? ws[lane] : 0;
        #pragma unroll
        for (int o = 1; o < 8; o <<= 1) {
            int u = __shfl_up_sync(FULL, y, o);
            if (lane >= o) y += u;
        }
        if (lane < 8) ws[lane] = y;
    }
    __syncthreads();
    int excl = x - v + (wd ? ws[wd - 1] : 0);
    if (i < n) {
        int off = g_boff[blockIdx.x] + excl;
        g_off[i] = off;
        g_cur[i] = off;
        g_dis[i] = rsqrtf(g_deg[i]);     // deg >= 1 (self-loop)
    }
}

// 4 edges per thread; build packed CSR entries
__global__ void k_scatter(const int* __restrict__ row, const int* __restrict__ col,
                          const float* __restrict__ w, int E) {
    int base = (blockIdx.x * blockDim.x + threadIdx.x) * 4;
    if (base >= E) return;
    int m = min(4, E - base);
    int r4[4], c4[4]; float w4[4];
    #pragma unroll
    for (int j = 0; j < 4; j++) {
        int idx = (j < m) ? base + j : base;
        r4[j] = __ldg(&row[idx]);
        c4[j] = __ldg(&col[idx]);
        w4[j] = __ldg(&w[idx]);
    }
    float nm[4];
    #pragma unroll
    for (int j = 0; j < 4; j++)
        nm[j] = __ldg(&g_dis[r4[j]]) * w4[j] * __ldg(&g_dis[c4[j]]);
    int pos[4];
    #pragma unroll
    for (int j = 0; j < 4; j++) if (j < m) pos[j] = atomicAdd(&g_cur[c4[j]], 1);
    #pragma unroll
    for (int j = 0; j < 4; j++) if (j < m)
        g_es[pos[j]] = make_int2(r4[j], __float_as_int(nm[j]));
}

// ---------------- layer 1 GEMM: xw = x @ W1 ----------------------------------
__global__ void k_xw1(const float* __restrict__ x, const float* __restrict__ W1,
                      int n, int F, int dst) {
    __shared__ float W1s[16 * H];
    for (int idx = threadIdx.x; idx < F * H; idx += blockDim.x)
        W1s[idx] = W1[idx];
    __syncthreads();
    int i = blockIdx.x * 4 + (threadIdx.x >> 6);
    int h = threadIdx.x & 63;
    if (i >= n) return;
    const float* xr = x + (size_t)i * F;
    float acc = 0.0f;
    for (int k = 0; k < F; k++) acc = fmaf(xr[k], W1s[k * H + h], acc);
    dst_buf(dst)[i * H + h] = acc;
}

// ---------------- gather core: 2 nodes/warp, 16 lanes/node, float4/lane ------
// Returns agg(lane16 columns) for node d. Both half-warps stay CONVERGED:
// batch count = max over the two halves; padded lanes contribute nm=0.
__device__ __forceinline__ float4 gather_node(const float* __restrict__ xw,
                                              int d, int hw, int l16) {
    int start = g_off[d];
    int end   = g_off[d + 1];
    int cnt   = end - start;
    float di  = g_dis[d];
    float4 self = *reinterpret_cast<const float4*>(&xw[(size_t)d * H + l16 * 4]);
    float dd = di * di;
    float4 acc = make_float4(dd * self.x, dd * self.y, dd * self.z, dd * self.w);

    int ocnt = __shfl_xor_sync(FULL, cnt, 16);
    int maxcnt = max(cnt, ocnt);

    for (int b = 0; b < maxcnt; b += 16) {
        int  pos   = b + l16;
        bool valid = pos < cnt;
        int2 p = g_es[valid ? (start + pos) : 0];
        int   r  = valid ? p.x : d;
        float nm = valid ? __int_as_float(p.y) : 0.0f;
        int jmax = min(maxcnt - b, 16);
        if (jmax == 16) {
            #pragma unroll
            for (int j = 0; j < 16; j++) {
                int sl = hw * 16 + j;
                int   rr = __shfl_sync(FULL, r, sl);
                float nn = __shfl_sync(FULL, nm, sl);
                float4 v = *reinterpret_cast<const float4*>(&xw[(size_t)rr * H + l16 * 4]);
                acc.x = fmaf(nn, v.x, acc.x);
                acc.y = fmaf(nn, v.y, acc.y);
                acc.z = fmaf(nn, v.z, acc.z);
                acc.w = fmaf(nn, v.w, acc.w);
            }
        } else {
            for (int j = 0; j < jmax; j++) {
                int sl = hw * 16 + j;
                int   rr = __shfl_sync(FULL, r, sl);
                float nn = __shfl_sync(FULL, nm, sl);
                float4 v = *reinterpret_cast<const float4*>(&xw[(size_t)rr * H + l16 * 4]);
                acc.x = fmaf(nn, v.x, acc.x);
                acc.y = fmaf(nn, v.y, acc.y);
                acc.z = fmaf(nn, v.z, acc.z);
                acc.w = fmaf(nn, v.w, acc.w);
            }
        }
    }
    return acc;
}

// ---------------- fused gather + sigmoid + next GEMM -------------------------
// 256 threads = 16 nodes/block.
__global__ void __launch_bounds__(256) k_gl(const float* __restrict__ W,
                                            const float* __restrict__ bprev,
                                            int n, int src) {
    __shared__ float Ws[H * H];
    __shared__ float hs[16][72];   // padded: 72*4=288B rows (16B-aligned, bank-offset 8)
    for (int idx = threadIdx.x; idx < H * H; idx += 256) Ws[idx] = W[idx];
    __syncthreads();

    const float* xw  = src_buf(src);
    float*       out = dst_buf(src ^ 1);
    int tid = threadIdx.x;
    int l16 = tid & 15;
    int hw  = (tid >> 4) & 1;
    int nib = tid >> 4;                 // node-in-block 0..15
    int d   = blockIdx.x * 16 + nib;
    bool live = d < n;
    int dd = live ? d : (n - 1);

    float4 acc = gather_node(xw, dd, hw, l16);

    float4 b4 = __ldg(reinterpret_cast<const float4*>(&bprev[l16 * 4]));
    float4 hv;
    hv.x = sigmoidf_(acc.x + b4.x);
    hv.y = sigmoidf_(acc.y + b4.y);
    hv.z = sigmoidf_(acc.z + b4.z);
    hv.w = sigmoidf_(acc.w + b4.w);
    *reinterpret_cast<float4*>(&hs[nib][l16 * 4]) = hv;
    __syncwarp();

    float4 o = make_float4(0.f, 0.f, 0.f, 0.f);
    #pragma unroll 8
    for (int k = 0; k < H; k++) {
        float hk = hs[nib][k];
        float4 wv = *reinterpret_cast<const float4*>(&Ws[k * H + l16 * 4]);
        o.x = fmaf(hk, wv.x, o.x);
        o.y = fmaf(hk, wv.y, o.y);
        o.z = fmaf(hk, wv.z, o.z);
        o.w = fmaf(hk, wv.w, o.w);
    }
    if (live)
        *reinterpret_cast<float4*>(&out[(size_t)d * H + l16 * 4]) = o;
}

// ---------------- head: gather + sigmoid + dot(Wl) + bl + max ----------------
__global__ void __launch_bounds__(256) k_ghead(const float* __restrict__ Wl,
                                               const float* __restrict__ bl,
                                               const float* __restrict__ b3,
                                               int n, int src) {
    const float* xw = src_buf(src);
    int tid = threadIdx.x;
    int l16 = tid & 15;
    int hw  = (tid >> 4) & 1;
    int d   = blockIdx.x * 16 + (tid >> 4);
    bool live = d < n;
    int dd = live ? d : (n - 1);

    float4 acc = gather_node(xw, dd, hw, l16);

    float4 b4 = __ldg(reinterpret_cast<const float4*>(&b3[l16 * 4]));
    float4 w4 = __ldg(reinterpret_cast<const float4*>(&Wl[l16 * 4]));
    float p = sigmoidf_(acc.x + b4.x) * w4.x
            + sigmoidf_(acc.y + b4.y) * w4.y
            + sigmoidf_(acc.z + b4.z) * w4.z
            + sigmoidf_(acc.w + b4.w) * w4.w;
    #pragma unroll
    for (int o = 8; o > 0; o >>= 1) p += __shfl_xor_sync(FULL, p, o);
    if (l16 == 0 && live) {
        float lg = p + __ldg(&bl[0]);
        g_logits[d] = lg;
        atomicMax(&g_maxbits, f2key(lg));
    }
}

// ---------------- softmax ----------------------------------------------------
__global__ void k_expsum(float* __restrict__ out, int n) {
    __shared__ float ssum[8];
    int i = blockIdx.x * blockDim.x + threadIdx.x;
    float mx = key2f(g_maxbits);
    float e = 0.0f;
    if (i < n) {
        e = expf(g_logits[i] - mx);
        out[i] = e;
    }
    #pragma unroll
    for (int o = 16; o > 0; o >>= 1) e += __shfl_xor_sync(FULL, e, o);
    int lane = threadIdx.x & 31, warp = threadIdx.x >> 5;
    if (lane == 0) ssum[warp] = e;
    __syncthreads();
    if (threadIdx.x == 0) {
        float s = 0.0f;
        #pragma unroll
        for (int w = 0; w < 8; w++) s += ssum[w];
        atomicAdd(&g_sum, s);
    }
}

__global__ void k_scale(float* __restrict__ out, int n) {
    int i = blockIdx.x * blockDim.x + threadIdx.x;
    if (i < n) out[i] *= (1.0f / g_sum);
}

// ---------------- launch -----------------------------------------------------
extern "C" void kernel_launch(void* const* d_in, const int* in_sizes, int n_in,
                              void* d_out, int out_size) {
    const float* x   = (const float*)d_in[0];
    const int*   edg = (const int*)d_in[1];
    const float* w   = (const float*)d_in[2];
    const float* W1  = (const float*)d_in[3];
    const float* b1  = (const float*)d_in[4];
    const float* W2  = (const float*)d_in[5];
    const float* b2  = (const float*)d_in[6];
    const float* W3  = (const float*)d_in[7];
    const float* b3  = (const float*)d_in[8];
    const float* Wl  = (const float*)d_in[9];
    const float* bl  = (const float*)d_in[10];
    float* out = (float*)d_out;

    int E = in_sizes[2];
    int F = in_sizes[3] / H;
    int n = in_sizes[0] / F;

    const int* row = edg;
    const int* col = edg + E;

    int nb_n  = (n + 255) / 256;             // node-chunk blocks (also scan B)
    int nb_e4 = (E + 1023) / 1024;           // 4 edges/thread
    int nb_g  = (n + 15) / 16;               // gather blocks (16 nodes each)

    k_init<<<nb_n, 256>>>(n);
    k_hist<<<nb_e4, 256>>>(col, w, E);
    k_s1<<<nb_n, 256>>>(n);
    k_s2<<<1, 256>>>(nb_n, E, n);
    k_s3<<<nb_n, 256>>>(n);
    k_scatter<<<nb_e4, 256>>>(row, col, w, E);

    k_xw1<<<(n + 3) / 4, 256>>>(x, W1, n, F, 0);   // -> buf0
    k_gl<<<nb_g, 256>>>(W2, b1, n, 0);             // buf0 -> buf1
    k_gl<<<nb_g, 256>>>(W3, b2, n, 1);             // buf1 -> buf0
    k_ghead<<<nb_g, 256>>>(Wl, bl, b3, n, 0);      // buf0 -> logits

    k_expsum<<<nb_n, 256>>>(out, n);
    k_scale<<<nb_n, 256>>>(out, n);
}

// round 5
// speedup vs baseline: 1.6406x; 1.0135x over previous
#include <cuda_runtime.h>
#include <cuda_fp16.h>
#include <stdint.h>

#define NMAX 65536
#define EMAX 2100000
#define H 64
#define FULL 0xffffffffu

// ---------------- scratch (device globals) ----------------------------------
// Convention: g_deg/g_cnt are ZERO on entry (zero at module load; re-zeroed by
// k_scale at the end of every call). g_sum is reset by k_s2 early in each call.
__device__ float g_deg[NMAX];
__device__ float g_dis[NMAX];
__device__ int   g_cnt[NMAX];
__device__ int   g_off[NMAX + 1];
__device__ int   g_cur[NMAX];
__device__ int   g_bsum[256];
__device__ int   g_boff[256];
__device__ __align__(16) int2    g_es[EMAX];       // {row, norm-bits}, CSR by col
__device__ __align__(16) __half2 g_hb0[NMAX * 32]; // 64 halves per node
__device__ __align__(16) __half2 g_hb1[NMAX * 32];
__device__ float g_sum;

// ---------------- helpers ----------------------------------------------------
__device__ __forceinline__ float sigmoidf_(float x) {
    return 1.0f / (1.0f + __expf(-x));
}
__device__ __forceinline__ const __half2* src_buf(int s) { return s ? g_hb1 : g_hb0; }
__device__ __forceinline__ __half2*       dst_buf(int s) { return s ? g_hb1 : g_hb0; }

// ---------------- prep kernels -----------------------------------------------
// 4 edges/thread; deg starts at 0 (self-loop folded into dis later)
__global__ void k_hist(const int* __restrict__ col, const float* __restrict__ w, int E) {
    int base = (blockIdx.x * blockDim.x + threadIdx.x) * 4;
    if (base >= E) return;
    int m = min(4, E - base);
    int c4[4]; float w4[4];
    #pragma unroll
    for (int j = 0; j < 4; j++) {
        int idx = (j < m) ? base + j : base;
        c4[j] = __ldg(&col[idx]);
        w4[j] = __ldg(&w[idx]);
    }
    #pragma unroll
    for (int j = 0; j < 4; j++) if (j < m) {
        atomicAdd(&g_deg[c4[j]], w4[j]);
        atomicAdd(&g_cnt[c4[j]], 1);
    }
}

// --- scan stage 1: per-256-chunk sums ---
__global__ void k_s1(int n) {
    __shared__ int ws[8];
    int t = threadIdx.x;
    int i = blockIdx.x * 256 + t;
    int v = (i < n) ? g_cnt[i] : 0;
    #pragma unroll
    for (int o = 16; o > 0; o >>= 1) v += __shfl_xor_sync(FULL, v, o);
    if ((t & 31) == 0) ws[t >> 5] = v;
    __syncthreads();
    if (t == 0) {
        int s = 0;
        #pragma unroll
        for (int wgi = 0; wgi < 8; wgi++) s += ws[wgi];
        g_bsum[blockIdx.x] = s;
    }
}

// --- scan stage 2: exclusive scan of block sums; also resets g_sum ---
__global__ void k_s2(int B, int E, int n) {
    __shared__ int ws[8];
    int t = threadIdx.x, lane = t & 31, wd = t >> 5;
    int v = (t < B) ? g_bsum[t] : 0;
    int x = v;
    #pragma unroll
    for (int o = 1; o < 32; o <<= 1) {
        int u = __shfl_up_sync(FULL, x, o);
        if (lane >= o) x += u;
    }
    if (lane == 31) ws[wd] = x;
    __syncthreads();
    if (wd == 0) {
        int y = (lane < 8) ? ws[lane] : 0;
        #pragma unroll
        for (int o = 1; o < 8; o <<= 1) {
            int u = __shfl_up_sync(FULL, y, o);
            if (lane >= o) y += u;
        }
        if (lane < 8) ws[lane] = y;
    }
    __syncthreads();
    int incl = x + (wd ? ws[wd - 1] : 0);
    if (t < B) g_boff[t] = incl - v;      // exclusive
    if (t == 0) { g_off[n] = E; g_sum = 0.0f; }
}

// --- scan stage 3: local exclusive scan + fixup; dis = rsqrt(1 + deg) ---
__global__ void k_s3(int n) {
    __shared__ int ws[8];
    int t = threadIdx.x, lane = t & 31, wd = t >> 5;
    int i = blockIdx.x * 256 + t;
    int v = (i < n) ? g_cnt[i] : 0;
    int x = v;
    #pragma unroll
    for (int o = 1; o < 32; o <<= 1) {
        int u = __shfl_up_sync(FULL, x, o);
        if (lane >= o) x += u;
    }
    if (lane == 31) ws[wd] = x;
    __syncthreads();
    if (wd == 0) {
        int y = (lane < 8) ? ws[lane] : 0;
        #pragma unroll
        for (int o = 1; o < 8; o <<= 1) {
            int u = __shfl_up_sync(FULL, y, o);
            if (lane >= o) y += u;
        }
        if (lane < 8) ws[lane] = y;
    }
    __syncthreads();
    int excl = x - v + (wd ? ws[wd - 1] : 0);
    if (i < n) {
        int off = g_boff[blockIdx.x] + excl;
        g_off[i] = off;
        g_cur[i] = off;
        g_dis[i] = rsqrtf(1.0f + g_deg[i]);   // self-loop weight 1
    }
}

// 4 edges/thread; build packed CSR entries
__global__ void k_scatter(const int* __restrict__ row, const int* __restrict__ col,
                          const float* __restrict__ w, int E) {
    int base = (blockIdx.x * blockDim.x + threadIdx.x) * 4;
    if (base >= E) return;
    int m = min(4, E - base);
    int r4[4], c4[4]; float w4[4];
    #pragma unroll
    for (int j = 0; j < 4; j++) {
        int idx = (j < m) ? base + j : base;
        r4[j] = __ldg(&row[idx]);
        c4[j] = __ldg(&col[idx]);
        w4[j] = __ldg(&w[idx]);
    }
    float nm[4];
    #pragma unroll
    for (int j = 0; j < 4; j++)
        nm[j] = __ldg(&g_dis[r4[j]]) * w4[j] * __ldg(&g_dis[c4[j]]);
    int pos[4];
    #pragma unroll
    for (int j = 0; j < 4; j++) if (j < m) pos[j] = atomicAdd(&g_cur[c4[j]], 1);
    #pragma unroll
    for (int j = 0; j < 4; j++) if (j < m)
        g_es[pos[j]] = make_int2(r4[j], __float_as_int(nm[j]));
}

// ---------------- layer 1 GEMM: xw = x @ W1 (fp16 out) -----------------------
// thread computes 2 adjacent outputs; 8 nodes/block
__global__ void k_xw1(const float* __restrict__ x, const float* __restrict__ W1,
                      int n, int F, int dst) {
    __shared__ float W1s[16 * H];
    for (int idx = threadIdx.x; idx < F * H; idx += blockDim.x)
        W1s[idx] = W1[idx];
    __syncthreads();
    int i = blockIdx.x * 8 + (threadIdx.x >> 5);
    int h2 = threadIdx.x & 31;
    if (i >= n) return;
    const float* xr = x + (size_t)i * F;
    float a0 = 0.0f, a1 = 0.0f;
    for (int k = 0; k < F; k++) {
        float xv = xr[k];
        a0 = fmaf(xv, W1s[k * H + 2 * h2], a0);
        a1 = fmaf(xv, W1s[k * H + 2 * h2 + 1], a1);
    }
    dst_buf(dst)[(size_t)i * 32 + h2] = __floats2half2_rn(a0, a1);
}

// ---------------- gather core: 4 nodes/warp, 8 lanes/node, fp16 rows ---------
// acc[8] accumulates fp32; padded lanes contribute nm=0; warp stays converged.
__device__ __forceinline__ void gather_node_h(const __half2* __restrict__ xw,
                                              int d, int gb, int l8,
                                              float* __restrict__ acc) {
    int start = g_off[d];
    int cnt   = g_off[d + 1] - start;
    float di  = g_dis[d];
    float dd  = di * di;
    uint4 su = *reinterpret_cast<const uint4*>(&xw[(size_t)d * 32 + l8 * 4]);
    const __half2* sh = reinterpret_cast<const __half2*>(&su);
    #pragma unroll
    for (int q = 0; q < 4; q++) {
        float2 f = __half22float2(sh[q]);
        acc[2 * q]     = dd * f.x;
        acc[2 * q + 1] = dd * f.y;
    }
    int c1 = max(cnt, __shfl_xor_sync(FULL, cnt, 8));
    int maxcnt = max(c1, __shfl_xor_sync(FULL, c1, 16));   // warp max

    for (int b = 0; b < maxcnt; b += 8) {
        int  pos   = b + l8;
        bool valid = pos < cnt;
        int2 p = g_es[valid ? start + pos : 0];
        int   r0 = valid ? p.x : 0;
        float n0 = valid ? __int_as_float(p.y) : 0.0f;
        #pragma unroll
        for (int j = 0; j < 8; j++) {
            int   r  = __shfl_sync(FULL, r0, gb + j);
            float nm = __shfl_sync(FULL, n0, gb + j);
            uint4 u = *reinterpret_cast<const uint4*>(&xw[(size_t)r * 32 + l8 * 4]);
            const __half2* hh = reinterpret_cast<const __half2*>(&u);
            #pragma unroll
            for (int q = 0; q < 4; q++) {
                float2 f = __half22float2(hh[q]);
                acc[2 * q]     = fmaf(nm, f.x, acc[2 * q]);
                acc[2 * q + 1] = fmaf(nm, f.y, acc[2 * q + 1]);
            }
        }
    }
}

// ---------------- fused gather + sigmoid + next GEMM -------------------------
// 256 threads = 32 nodes/block (8 warps x 4 nodes).
__global__ void __launch_bounds__(256) k_gl(const float* __restrict__ W,
                                            const float* __restrict__ bprev,
                                            int n, int src) {
    __shared__ float Ws[H * H];
    __shared__ float hs[32][72];
    for (int idx = threadIdx.x; idx < H * H; idx += 256) Ws[idx] = W[idx];
    __syncthreads();

    const __half2* xw  = src_buf(src);
    __half2*       out = dst_buf(src ^ 1);
    int tid = threadIdx.x;
    int lane = tid & 31;
    int l8 = lane & 7, gb = lane & 24;
    int nib = tid >> 3;                 // node-in-block 0..31
    int d   = blockIdx.x * 32 + nib;
    bool live = d < n;
    int dd = live ? d : (n - 1);

    float acc[8];
    gather_node_h(xw, dd, gb, l8, acc);

    float4 b0 = __ldg(reinterpret_cast<const float4*>(&bprev[l8 * 8]));
    float4 b1 = __ldg(reinterpret_cast<const float4*>(&bprev[l8 * 8 + 4]));
    float hv[8];
    hv[0] = sigmoidf_(acc[0] + b0.x); hv[1] = sigmoidf_(acc[1] + b0.y);
    hv[2] = sigmoidf_(acc[2] + b0.z); hv[3] = sigmoidf_(acc[3] + b0.w);
    hv[4] = sigmoidf_(acc[4] + b1.x); hv[5] = sigmoidf_(acc[5] + b1.y);
    hv[6] = sigmoidf_(acc[6] + b1.z); hv[7] = sigmoidf_(acc[7] + b1.w);
    *reinterpret_cast<float4*>(&hs[nib][l8 * 8])     = make_float4(hv[0], hv[1], hv[2], hv[3]);
    *reinterpret_cast<float4*>(&hs[nib][l8 * 8 + 4]) = make_float4(hv[4], hv[5], hv[6], hv[7]);
    __syncwarp();

    float o[8] = {0, 0, 0, 0, 0, 0, 0, 0};
    #pragma unroll 8
    for (int k = 0; k < H; k++) {
        float hk = hs[nib][k];
        float4 w0 = *reinterpret_cast<const float4*>(&Ws[k * H + l8 * 8]);
        float4 w1 = *reinterpret_cast<const float4*>(&Ws[k * H + l8 * 8 + 4]);
        o[0] = fmaf(hk, w0.x, o[0]); o[1] = fmaf(hk, w0.y, o[1]);
        o[2] = fmaf(hk, w0.z, o[2]); o[3] = fmaf(hk, w0.w, o[3]);
        o[4] = fmaf(hk, w1.x, o[4]); o[5] = fmaf(hk, w1.y, o[5]);
        o[6] = fmaf(hk, w1.z, o[6]); o[7] = fmaf(hk, w1.w, o[7]);
    }
    if (live) {
        __half2 ph[4];
        #pragma unroll
        for (int q = 0; q < 4; q++) ph[q] = __floats2half2_rn(o[2 * q], o[2 * q + 1]);
        *reinterpret_cast<uint4*>(&out[(size_t)d * 32 + l8 * 4]) =
            *reinterpret_cast<uint4*>(ph);
    }
}

// ---------------- head: gather + sigmoid + dot(Wl) + exp + sum ---------------
// Writes exp(logit) directly to out (logits bounded, no max-shift needed).
__global__ void __launch_bounds__(256) k_ghead(const float* __restrict__ Wl,
                                               const float* __restrict__ bl,
                                               const float* __restrict__ b3,
                                               float* __restrict__ out,
                                               int n, int src) {
    const __half2* xw = src_buf(src);
    int tid = threadIdx.x;
    int lane = tid & 31;
    int l8 = lane & 7, gb = lane & 24;
    int d = blockIdx.x * 32 + (tid >> 3);
    bool live = d < n;
    int dd = live ? d : (n - 1);

    float acc[8];
    gather_node_h(xw, dd, gb, l8, acc);

    float4 b0 = __ldg(reinterpret_cast<const float4*>(&b3[l8 * 8]));
    float4 b1 = __ldg(reinterpret_cast<const float4*>(&b3[l8 * 8 + 4]));
    float4 w0 = __ldg(reinterpret_cast<const float4*>(&Wl[l8 * 8]));
    float4 w1 = __ldg(reinterpret_cast<const float4*>(&Wl[l8 * 8 + 4]));
    float p = sigmoidf_(acc[0] + b0.x) * w0.x
            + sigmoidf_(acc[1] + b0.y) * w0.y
            + sigmoidf_(acc[2] + b0.z) * w0.z
            + sigmoidf_(acc[3] + b0.w) * w0.w
            + sigmoidf_(acc[4] + b1.x) * w1.x
            + sigmoidf_(acc[5] + b1.y) * w1.y
            + sigmoidf_(acc[6] + b1.z) * w1.z
            + sigmoidf_(acc[7] + b1.w) * w1.w;
    #pragma unroll
    for (int o = 4; o > 0; o >>= 1) p += __shfl_xor_sync(FULL, p, o);

    float e = 0.0f;
    if (l8 == 0 && live) {
        e = expf(p + __ldg(&bl[0]));
        out[d] = e;
    }
    // sum the 4 group leaders onto lane 0, one RED per warp
    e += __shfl_xor_sync(FULL, e, 8);
    e += __shfl_xor_sync(FULL, e, 16);
    if (lane == 0) atomicAdd(&g_sum, e);
}

// ---------------- normalize + cleanup for next call --------------------------
__global__ void k_scale(float* __restrict__ out, int n) {
    int i = blockIdx.x * blockDim.x + threadIdx.x;
    if (i < n) {
        out[i] *= (1.0f / g_sum);
        g_deg[i] = 0.0f;
        g_cnt[i] = 0;
    }
}

// ---------------- launch -----------------------------------------------------
extern "C" void kernel_launch(void* const* d_in, const int* in_sizes, int n_in,
                              void* d_out, int out_size) {
    const float* x   = (const float*)d_in[0];
    const int*   edg = (const int*)d_in[1];
    const float* w   = (const float*)d_in[2];
    const float* W1  = (const float*)d_in[3];
    const float* b1  = (const float*)d_in[4];
    const float* W2  = (const float*)d_in[5];
    const float* b2  = (const float*)d_in[6];
    const float* W3  = (const float*)d_in[7];
    const float* b3  = (const float*)d_in[8];
    const float* Wl  = (const float*)d_in[9];
    const float* bl  = (const float*)d_in[10];
    float* out = (float*)d_out;

    int E = in_sizes[2];
    int F = in_sizes[3] / H;
    int n = in_sizes[0] / F;

    const int* row = edg;
    const int* col = edg + E;

    int nb_n  = (n + 255) / 256;
    int nb_e4 = (E + 1023) / 1024;
    int nb_g  = (n + 31) / 32;

    k_hist<<<nb_e4, 256>>>(col, w, E);
    k_s1<<<nb_n, 256>>>(n);
    k_s2<<<1, 256>>>(nb_n, E, n);
    k_s3<<<nb_n, 256>>>(n);
    k_scatter<<<nb_e4, 256>>>(row, col, w, E);

    k_xw1<<<(n + 7) / 8, 256>>>(x, W1, n, F, 0);       // -> hb0
    k_gl<<<nb_g, 256>>>(W2, b1, n, 0);                 // hb0 -> hb1
    k_gl<<<nb_g, 256>>>(W3, b2, n, 1);                 // hb1 -> hb0
    k_ghead<<<nb_g, 256>>>(Wl, bl, b3, out, n, 0);     // hb0 -> exp(logits)

    k_scale<<<nb_n, 256>>>(out, n);
}